// round 2
// baseline (speedup 1.0000x reference)
#include <cuda_runtime.h>
#include <math.h>

#define SEQ   512
#define BATCH 32
#define ROWS  16384        // BATCH*SEQ
#define HID   300
#define HDIM  64
#define NH    8
#define DH    8
#define NL    6
#define FF    1200
#define NC    1000

// ---------------- scratch (static device globals; no allocation) ----------------
__device__ float g_acc [ROWS*HID];
__device__ float g_out [ROWS*HID];
__device__ float g_xa  [ROWS*HID];
__device__ float g_tmp [ROWS*HID];
__device__ float g_q   [ROWS*HDIM];
__device__ float g_k   [ROWS*HDIM];
__device__ float g_v   [ROWS*HDIM];
__device__ float g_attn[ROWS*HDIM];
__device__ float g_ffh [ROWS*FF];
__device__ float g_pe  [SEQ*HID];
__device__ float g_sums[BATCH*HID];
__device__ float g_logits[BATCH*NC];

// ---------------- positional encoding table ----------------
__global__ void pe_kernel(float* __restrict__ pe) {
    int s = blockIdx.x;
    for (int c = threadIdx.x; c < HID; c += blockDim.x) {
        double expo = (double)(c & ~1) / (double)HID;
        double ang  = (double)s * exp(-expo * 9.210340371976182736); // ln(10000)
        pe[s*HID + c] = (c & 1) ? (float)cos(ang) : (float)sin(ang);
    }
}

// acc = 2*emb[token] + PE   (x2 = emb+PE; acc = x2 + x1)
__global__ void embed_kernel(const int* __restrict__ tok,
                             const float* __restrict__ emb,
                             const float* __restrict__ pe,
                             float* __restrict__ accb) {
    int row = blockIdx.x;
    int s   = row & (SEQ - 1);
    long long t = tok[row];
    const float* er = emb + t * HID;
    const float* pr = pe + s * HID;
    for (int c = threadIdx.x; c < HID; c += blockDim.x) {
        accb[row*HID + c] = 2.f * er[c] + pr[c];
    }
}

// ---------------- generic tiled fp32 GEMM: C = A(MxK) @ B(KxN) [+bias][+res][relu] ----------------
template<bool RELU, bool BIAS, bool RES>
__global__ void gemm64(const float* __restrict__ A, const float* __restrict__ B,
                       const float* __restrict__ bias, const float* __restrict__ res,
                       float* __restrict__ C, int M, int N, int K) {
    __shared__ float As [16][65];
    __shared__ float Bsm[16][65];
    const int tid = threadIdx.x;            // 256 threads
    const int bm  = blockIdx.y * 64;
    const int bn  = blockIdx.x * 64;
    const int tx  = tid & 15;
    const int ty  = tid >> 4;
    const int lm  = tid >> 4;               // 0..15
    const int lk  = tid & 15;
    const int lk2 = tid >> 6;               // 0..3
    const int ln  = tid & 63;

    float acc[4][4];
#pragma unroll
    for (int i = 0; i < 4; i++)
#pragma unroll
        for (int j = 0; j < 4; j++) acc[i][j] = 0.f;

    for (int k0 = 0; k0 < K; k0 += 16) {
#pragma unroll
        for (int i = 0; i < 4; i++) {
            int m = lm + i * 16;
            float v = 0.f;
            if (k0 + lk < K) v = A[(size_t)(bm + m) * K + k0 + lk];
            As[lk][m] = v;
        }
#pragma unroll
        for (int i = 0; i < 4; i++) {
            int kk = lk2 + i * 4;
            float v = 0.f;
            if (k0 + kk < K && bn + ln < N) v = B[(size_t)(k0 + kk) * N + bn + ln];
            Bsm[kk][ln] = v;
        }
        __syncthreads();
#pragma unroll
        for (int kk = 0; kk < 16; kk++) {
            float a[4], bv[4];
#pragma unroll
            for (int i = 0; i < 4; i++) a[i]  = As [kk][ty*4 + i];
#pragma unroll
            for (int j = 0; j < 4; j++) bv[j] = Bsm[kk][tx*4 + j];
#pragma unroll
            for (int i = 0; i < 4; i++)
#pragma unroll
                for (int j = 0; j < 4; j++)
                    acc[i][j] += a[i] * bv[j];
        }
        __syncthreads();
    }
#pragma unroll
    for (int i = 0; i < 4; i++) {
        int m = bm + ty*4 + i;
#pragma unroll
        for (int j = 0; j < 4; j++) {
            int n = bn + tx*4 + j;
            if (n < N) {
                float v = acc[i][j];
                if (BIAS) v += bias[n];
                if (RES)  v += res[(size_t)m * N + n];
                if (RELU) v = fmaxf(v, 0.f);
                C[(size_t)m * N + n] = v;
            }
        }
    }
}

// ---------------- attention: one block per (head, batch), one thread per query ----------------
__global__ void attn_kernel(const float* __restrict__ Q, const float* __restrict__ Kb,
                            const float* __restrict__ Vb, const int* __restrict__ tok,
                            float* __restrict__ O) {
    const int h = blockIdx.x;
    const int b = blockIdx.y;
    __shared__ float Ks[SEQ][8];
    __shared__ float Vs[SEQ][8];
    __shared__ float msk[SEQ];
    const int t = threadIdx.x;       // 512
    const int base = b * SEQ;

#pragma unroll
    for (int d = 0; d < 8; d++) {
        Ks[t][d] = Kb[(size_t)(base + t) * HDIM + d*8 + h];
        Vs[t][d] = Vb[(size_t)(base + t) * HDIM + d*8 + h];
    }
    msk[t] = (tok[base + t] == 0) ? 1.f : 0.f;
    __syncthreads();

    float q[8];
#pragma unroll
    for (int d = 0; d < 8; d++) q[d] = Q[(size_t)(base + t) * HDIM + d*8 + h];

    const float scale = 0.05773502691896258f;  // 1/sqrt(300)
    float m = -1e30f, ssum = 0.f, o[8];
#pragma unroll
    for (int d = 0; d < 8; d++) o[d] = 0.f;

    for (int k = 0; k < SEQ; k++) {
        float s = 0.f;
#pragma unroll
        for (int d = 0; d < 8; d++) s += q[d] * Ks[k][d];
        s *= scale;
        if (msk[k] != 0.f) s = -1e9f;
        if (s <= m) {
            float p = __expf(s - m);
            ssum += p;
#pragma unroll
            for (int d = 0; d < 8; d++) o[d] += p * Vs[k][d];
        } else {
            float corr = __expf(m - s);
            ssum = ssum * corr + 1.f;
#pragma unroll
            for (int d = 0; d < 8; d++) o[d] = o[d] * corr + Vs[k][d];
            m = s;
        }
    }
    float inv = 1.f / ssum;
#pragma unroll
    for (int d = 0; d < 8; d++)
        O[(size_t)(base + t) * HDIM + h*8 + d] = o[d] * inv;   // head-major concat
}

// ---------------- row LayerNorm over HID, ddof=1, eps 1e-8; optionally acc += y ----------------
template<bool ACC>
__global__ void ln_kernel(const float* __restrict__ in, float* __restrict__ outp,
                          const float* __restrict__ g, const float* __restrict__ bt,
                          float* __restrict__ accb) {
    const int row = blockIdx.x;
    const int t = threadIdx.x;       // 128
    __shared__ float red[128];
    const float* x = in + (size_t)row * HID;

    float v[3]; int c[3];
    float s = 0.f;
#pragma unroll
    for (int i = 0; i < 3; i++) {
        c[i] = t + i * 128;
        v[i] = (c[i] < HID) ? x[c[i]] : 0.f;
        s += v[i];
    }
    red[t] = s; __syncthreads();
    for (int st = 64; st > 0; st >>= 1) { if (t < st) red[t] += red[t + st]; __syncthreads(); }
    float mu = red[0] / HID;
    __syncthreads();
    float sq = 0.f;
#pragma unroll
    for (int i = 0; i < 3; i++) {
        if (c[i] < HID) { float d = v[i] - mu; sq += d * d; }
    }
    red[t] = sq; __syncthreads();
    for (int st = 64; st > 0; st >>= 1) { if (t < st) red[t] += red[t + st]; __syncthreads(); }
    float var = red[0] / (HID - 1);
    float inv = rsqrtf(var + 1e-8f);
    float gg = g[0], bb = bt[0];
#pragma unroll
    for (int i = 0; i < 3; i++) {
        if (c[i] < HID) {
            float y = gg * (v[i] - mu) * inv + bb;
            outp[(size_t)row * HID + c[i]] = y;
            if (ACC) accb[(size_t)row * HID + c[i]] += y;
        }
    }
}

// ---------------- sum over sequence: (B,S,HID) -> (B,HID) ----------------
__global__ void seqsum_kernel(const float* __restrict__ in, float* __restrict__ sums) {
    int b = blockIdx.x;
    int c = threadIdx.x;
    if (c < HID) {
        float a = 0.f;
        const float* p = in + (size_t)b * SEQ * HID + c;
        for (int s = 0; s < SEQ; s++) a += p[(size_t)s * HID];
        sums[b * HID + c] = a;
    }
}

// ---------------- classifier: (B,HID) @ (HID,NC) ----------------
__global__ void classify_kernel(const float* __restrict__ sums, const float* __restrict__ Vd,
                                float* __restrict__ logits) {
    int b = blockIdx.y;
    int c = blockIdx.x * 256 + threadIdx.x;
    __shared__ float srow[HID];
    for (int i = threadIdx.x; i < HID; i += 256) srow[i] = sums[b * HID + i];
    __syncthreads();
    if (c < NC) {
        float a = 0.f;
        for (int k = 0; k < HID; k++) a += srow[k] * Vd[(size_t)k * NC + c];
        logits[b * NC + c] = a;
    }
}

// ---------------- final LN (ddof=1) + softmax over NC ----------------
__global__ void final_kernel(const float* __restrict__ logits,
                             const float* __restrict__ gf, const float* __restrict__ bf,
                             float* __restrict__ outp) {
    const int b = blockIdx.x;
    const int t = threadIdx.x;   // 256
    __shared__ float buf[NC];
    __shared__ float red[256];
    const float* x = logits + (size_t)b * NC;

    float s = 0.f;
    for (int c = t; c < NC; c += 256) { float v = x[c]; buf[c] = v; s += v; }
    red[t] = s; __syncthreads();
    for (int st = 128; st > 0; st >>= 1) { if (t < st) red[t] += red[t + st]; __syncthreads(); }
    float mu = red[0] / NC;
    __syncthreads();

    float sq = 0.f;
    for (int c = t; c < NC; c += 256) { float d = buf[c] - mu; sq += d * d; }
    red[t] = sq; __syncthreads();
    for (int st = 128; st > 0; st >>= 1) { if (t < st) red[t] += red[t + st]; __syncthreads(); }
    float inv = rsqrtf(red[0] / (NC - 1) + 1e-8f);
    float gg = gf[0], bb = bf[0];
    __syncthreads();

    for (int c = t; c < NC; c += 256) buf[c] = gg * (buf[c] - mu) * inv + bb;
    __syncthreads();

    float mx = -1e30f;
    for (int c = t; c < NC; c += 256) mx = fmaxf(mx, buf[c]);
    red[t] = mx; __syncthreads();
    for (int st = 128; st > 0; st >>= 1) { if (t < st) red[t] = fmaxf(red[t], red[t + st]); __syncthreads(); }
    float rmax = red[0];
    __syncthreads();

    float es = 0.f;
    for (int c = t; c < NC; c += 256) es += __expf(buf[c] - rmax);
    red[t] = es; __syncthreads();
    for (int st = 128; st > 0; st >>= 1) { if (t < st) red[t] += red[t + st]; __syncthreads(); }
    float invs = 1.f / red[0];
    __syncthreads();

    for (int c = t; c < NC; c += 256) outp[(size_t)b * NC + c] = __expf(buf[c] - rmax) * invs;
}

// ---------------- launch ----------------
extern "C" void kernel_launch(void* const* d_in, const int* in_sizes, int n_in,
                              void* d_out, int out_size) {
    const int*   xk  = (const int*)  d_in[0];
    const float* emb = (const float*)d_in[1];
    const float* WQ  = (const float*)d_in[2];
    const float* WK  = (const float*)d_in[3];
    const float* WV  = (const float*)d_in[4];
    const float* WO  = (const float*)d_in[5];
    const float* W1  = (const float*)d_in[6];
    const float* b1  = (const float*)d_in[7];
    const float* W2  = (const float*)d_in[8];
    const float* b2  = (const float*)d_in[9];
    const float* g1  = (const float*)d_in[10];
    const float* be1 = (const float*)d_in[11];
    const float* g2  = (const float*)d_in[12];
    const float* be2 = (const float*)d_in[13];
    const float* Vd  = (const float*)d_in[14];
    const float* gf  = (const float*)d_in[15];
    const float* bf  = (const float*)d_in[16];
    float* outp = (float*)d_out;

    float *acc, *outb, *xa, *tmp, *q, *k, *v, *attn, *ffh, *pe, *sums, *logits;
    cudaGetSymbolAddress((void**)&acc,   g_acc);
    cudaGetSymbolAddress((void**)&outb,  g_out);
    cudaGetSymbolAddress((void**)&xa,    g_xa);
    cudaGetSymbolAddress((void**)&tmp,   g_tmp);
    cudaGetSymbolAddress((void**)&q,     g_q);
    cudaGetSymbolAddress((void**)&k,     g_k);
    cudaGetSymbolAddress((void**)&v,     g_v);
    cudaGetSymbolAddress((void**)&attn,  g_attn);
    cudaGetSymbolAddress((void**)&ffh,   g_ffh);
    cudaGetSymbolAddress((void**)&pe,    g_pe);
    cudaGetSymbolAddress((void**)&sums,  g_sums);
    cudaGetSymbolAddress((void**)&logits,g_logits);

    pe_kernel<<<SEQ, 128>>>(pe);
    embed_kernel<<<ROWS, 128>>>(xk, emb, pe, acc);

    for (int l = 0; l < NL; l++) {
        const float* wq = WQ + (size_t)l * HID * HDIM;
        const float* wk = WK + (size_t)l * HID * HDIM;
        const float* wv = WV + (size_t)l * HID * HDIM;
        const float* wo = WO + (size_t)l * HDIM * HID;
        const float* w1 = W1 + (size_t)l * HID * FF;
        const float* w2 = W2 + (size_t)l * FF * HID;
        const float* bb1 = b1 + (size_t)l * FF;
        const float* bb2 = b2 + (size_t)l * HID;

        dim3 gq((HDIM + 63) / 64, ROWS / 64);
        gemm64<false,false,false><<<gq, 256>>>(acc, wq, nullptr, nullptr, q, ROWS, HDIM, HID);
        gemm64<false,false,false><<<gq, 256>>>(acc, wk, nullptr, nullptr, k, ROWS, HDIM, HID);
        gemm64<false,false,false><<<gq, 256>>>(acc, wv, nullptr, nullptr, v, ROWS, HDIM, HID);

        attn_kernel<<<dim3(NH, BATCH), SEQ>>>(q, k, v, xk, attn);

        dim3 go((HID + 63) / 64, ROWS / 64);
        gemm64<false,false,true><<<go, 256>>>(attn, wo, nullptr, acc, tmp, ROWS, HID, HDIM);
        ln_kernel<false><<<ROWS, 128>>>(tmp, xa, g1 + l, be1 + l, nullptr);

        dim3 gf1((FF + 63) / 64, ROWS / 64);
        gemm64<true,true,false><<<gf1, 256>>>(xa, w1, bb1, nullptr, ffh, ROWS, FF, HID);
        gemm64<false,true,true><<<go, 256>>>(ffh, w2, bb2, xa, tmp, ROWS, HID, FF);
        ln_kernel<true><<<ROWS, 128>>>(tmp, outb, g2 + l, be2 + l, acc);
    }

    seqsum_kernel<<<BATCH, 320>>>(outb, sums);
    classify_kernel<<<dim3((NC + 255) / 256, BATCH), 256>>>(sums, Vd, logits);
    final_kernel<<<BATCH, 256>>>(logits, gf, bf, outp);
}

// round 3
// speedup vs baseline: 2.2802x; 2.2802x over previous
#include <cuda_runtime.h>
#include <math.h>

#define SEQ   512
#define BATCH 32
#define ROWS  16384        // BATCH*SEQ
#define HID   300
#define HDIM  64
#define NH    8
#define DH    8
#define NL    6
#define FF    1200
#define NC    1000

// ---------------- scratch (static device globals; no allocation) ----------------
__device__ float g_acc [ROWS*HID];
__device__ float g_out [ROWS*HID];
__device__ float g_xa  [ROWS*HID];
__device__ float g_tmp [ROWS*HID];
__device__ float g_q   [ROWS*HDIM];
__device__ float g_k   [ROWS*HDIM];
__device__ float g_v   [ROWS*HDIM];
__device__ float g_attn[ROWS*HDIM];
__device__ float g_ffh [ROWS*FF];
__device__ float g_pe  [SEQ*HID];
__device__ float g_sums[BATCH*HID];
__device__ float g_logits[BATCH*NC];

// ---------------- positional encoding table ----------------
__global__ void pe_kernel(float* __restrict__ pe) {
    int s = blockIdx.x;
    for (int c = threadIdx.x; c < HID; c += blockDim.x) {
        double expo = (double)(c & ~1) / (double)HID;
        double ang  = (double)s * exp(-expo * 9.210340371976182736); // ln(10000)
        pe[s*HID + c] = (c & 1) ? (float)cos(ang) : (float)sin(ang);
    }
}

// acc = 2*emb[token] + PE   (x2 = emb+PE; acc = x2 + x1)
__global__ void embed_kernel(const int* __restrict__ tok,
                             const float* __restrict__ emb,
                             const float* __restrict__ pe,
                             float* __restrict__ accb) {
    int row = blockIdx.x;
    int s   = row & (SEQ - 1);
    long long t = tok[row];
    const float* er = emb + t * HID;
    const float* pr = pe + s * HID;
    for (int c = threadIdx.x; c < HID; c += blockDim.x) {
        accb[row*HID + c] = 2.f * er[c] + pr[c];
    }
}

// ================= tf32 tensor-core GEMM =================
// C(MxN) = A(MxK, row-major) @ B(KxN, row-major) [+bias][+res][relu]
// block tile 128x64, BK=16, 256 threads = 8 warps, warp tile 32x32 (2x4 m16n8k8)

__device__ __forceinline__ unsigned f2tf(float f) {
    unsigned u;
    asm("cvt.rna.tf32.f32 %0, %1;" : "=r"(u) : "f"(f));
    return u;
}

__device__ __forceinline__ void mma_tf32(float d[4], const unsigned a[4],
                                         const unsigned b[2], const float c[4]) {
    asm volatile(
        "mma.sync.aligned.m16n8k8.row.col.f32.tf32.tf32.f32 "
        "{%0,%1,%2,%3}, {%4,%5,%6,%7}, {%8,%9}, {%10,%11,%12,%13};\n"
        : "=f"(d[0]), "=f"(d[1]), "=f"(d[2]), "=f"(d[3])
        : "r"(a[0]), "r"(a[1]), "r"(a[2]), "r"(a[3]),
          "r"(b[0]), "r"(b[1]),
          "f"(c[0]), "f"(c[1]), "f"(c[2]), "f"(c[3]));
}

#define AS_LD 136   // 136 % 32 == 8 -> conflict-free fragment loads
#define BS_LD 72    //  72 % 32 == 8

__device__ __forceinline__ void load_tiles(const float* __restrict__ A,
                                           const float* __restrict__ B,
                                           int N, int K, int bm, int bn, int k0, int tid,
                                           float4 ra[2], float4& rb) {
#pragma unroll
    for (int j = 0; j < 2; j++) {
        int idx = tid + j * 256;
        int r = idx >> 2, kg = idx & 3;
        int col = k0 + kg * 4;
        const float* p = A + (size_t)(bm + r) * K + col;
        float4 v = make_float4(0.f, 0.f, 0.f, 0.f);
        if (col + 3 < K) v = *(const float4*)p;
        else {
            if (col + 0 < K) v.x = p[0];
            if (col + 1 < K) v.y = p[1];
            if (col + 2 < K) v.z = p[2];
        }
        ra[j] = v;
    }
    {
        int br = tid >> 4, ng = tid & 15;
        int row = k0 + br, col = bn + ng * 4;
        float4 v = make_float4(0.f, 0.f, 0.f, 0.f);
        if (row < K) {
            const float* p = B + (size_t)row * N + col;
            if (col + 3 < N) v = *(const float4*)p;
            else {
                if (col + 0 < N) v.x = p[0];
                if (col + 1 < N) v.y = p[1];
                if (col + 2 < N) v.z = p[2];
            }
        }
        rb = v;
    }
}

template<bool RELU, bool BIAS, bool RES>
__device__ __forceinline__ void gemm_body(const float* __restrict__ A,
                                          const float* __restrict__ B,
                                          const float* __restrict__ bias,
                                          const float* __restrict__ res,
                                          float* __restrict__ C,
                                          int N, int K, int bm, int bn) {
    __shared__ unsigned As[16][AS_LD];
    __shared__ unsigned Bs[16][BS_LD];

    const int tid = threadIdx.x;
    const int lane = tid & 31, warp = tid >> 5;
    const int gid = lane >> 2, tig = lane & 3;
    const int rowb = (warp >> 1) * 32;     // 0,32,64,96
    const int nb   = (warp & 1) * 32;      // 0,32

    float acc[2][4][4];
#pragma unroll
    for (int mt = 0; mt < 2; mt++)
#pragma unroll
        for (int nt = 0; nt < 4; nt++)
#pragma unroll
            for (int i = 0; i < 4; i++) acc[mt][nt][i] = 0.f;

    float4 ra[2]; float4 rb;
    load_tiles(A, B, N, K, bm, bn, 0, tid, ra, rb);

    for (int k0 = 0; k0 < K; k0 += 16) {
        // regs -> smem (with tf32 rounding)
#pragma unroll
        for (int j = 0; j < 2; j++) {
            int idx = tid + j * 256;
            int r = idx >> 2, kg = idx & 3;
            As[kg * 4 + 0][r] = f2tf(ra[j].x);
            As[kg * 4 + 1][r] = f2tf(ra[j].y);
            As[kg * 4 + 2][r] = f2tf(ra[j].z);
            As[kg * 4 + 3][r] = f2tf(ra[j].w);
        }
        {
            int br = tid >> 4, ng = tid & 15;
            Bs[br][ng * 4 + 0] = f2tf(rb.x);
            Bs[br][ng * 4 + 1] = f2tf(rb.y);
            Bs[br][ng * 4 + 2] = f2tf(rb.z);
            Bs[br][ng * 4 + 3] = f2tf(rb.w);
        }
        __syncthreads();

        if (k0 + 16 < K) load_tiles(A, B, N, K, bm, bn, k0 + 16, tid, ra, rb);

#pragma unroll
        for (int ks = 0; ks < 2; ks++) {
            const int kk = ks * 8;
            unsigned af[2][4], bf[4][2];
#pragma unroll
            for (int mt = 0; mt < 2; mt++) {
                int r0 = rowb + mt * 16 + gid;
                af[mt][0] = As[kk + tig    ][r0];
                af[mt][1] = As[kk + tig    ][r0 + 8];
                af[mt][2] = As[kk + tig + 4][r0];
                af[mt][3] = As[kk + tig + 4][r0 + 8];
            }
#pragma unroll
            for (int nt = 0; nt < 4; nt++) {
                int c0 = nb + nt * 8 + gid;
                bf[nt][0] = Bs[kk + tig    ][c0];
                bf[nt][1] = Bs[kk + tig + 4][c0];
            }
#pragma unroll
            for (int mt = 0; mt < 2; mt++)
#pragma unroll
                for (int nt = 0; nt < 4; nt++)
                    mma_tf32(acc[mt][nt], af[mt], bf[nt], acc[mt][nt]);
        }
        __syncthreads();
    }

    // epilogue
#pragma unroll
    for (int mt = 0; mt < 2; mt++) {
        int row0 = bm + rowb + mt * 16 + gid;
#pragma unroll
        for (int nt = 0; nt < 4; nt++) {
            int col = bn + nb + nt * 8 + 2 * tig;
#pragma unroll
            for (int half = 0; half < 2; half++) {
                int row = row0 + half * 8;
                float v0 = acc[mt][nt][half * 2 + 0];
                float v1 = acc[mt][nt][half * 2 + 1];
                if (col < N) {
                    if (BIAS) v0 += bias[col];
                    if (RES)  v0 += res[(size_t)row * N + col];
                    if (RELU) v0 = fmaxf(v0, 0.f);
                    C[(size_t)row * N + col] = v0;
                }
                if (col + 1 < N) {
                    if (BIAS) v1 += bias[col + 1];
                    if (RES)  v1 += res[(size_t)row * N + col + 1];
                    if (RELU) v1 = fmaxf(v1, 0.f);
                    C[(size_t)row * N + col + 1] = v1;
                }
            }
        }
    }
}

template<bool RELU, bool BIAS, bool RES>
__global__ void __launch_bounds__(256) gemm_tc(const float* __restrict__ A,
                                               const float* __restrict__ B,
                                               const float* __restrict__ bias,
                                               const float* __restrict__ res,
                                               float* __restrict__ C,
                                               int N, int K) {
    gemm_body<RELU, BIAS, RES>(A, B, bias, res, C, N, K,
                               blockIdx.y * 128, blockIdx.x * 64);
}

// fused QKV: grid (1, M/128, 3)
__global__ void __launch_bounds__(256) qkv_tc(const float* __restrict__ A,
                                              const float* __restrict__ WQa,
                                              const float* __restrict__ WKa,
                                              const float* __restrict__ WVa,
                                              float* __restrict__ Q,
                                              float* __restrict__ Kk,
                                              float* __restrict__ V) {
    const float* B = (blockIdx.z == 0) ? WQa : (blockIdx.z == 1) ? WKa : WVa;
    float* C = (blockIdx.z == 0) ? Q : (blockIdx.z == 1) ? Kk : V;
    gemm_body<false, false, false>(A, B, nullptr, nullptr, C, HDIM, HID,
                                   blockIdx.y * 128, 0);
}

// ---------------- attention: one block per (head, batch), one thread per query ----------------
__global__ void attn_kernel(const float* __restrict__ Q, const float* __restrict__ Kb,
                            const float* __restrict__ Vb, const int* __restrict__ tok,
                            float* __restrict__ O) {
    const int h = blockIdx.x;
    const int b = blockIdx.y;
    __shared__ float Ks[SEQ][8];
    __shared__ float Vs[SEQ][8];
    __shared__ float msk[SEQ];
    const int t = threadIdx.x;       // 512
    const int base = b * SEQ;

#pragma unroll
    for (int d = 0; d < 8; d++) {
        Ks[t][d] = Kb[(size_t)(base + t) * HDIM + d*8 + h];
        Vs[t][d] = Vb[(size_t)(base + t) * HDIM + d*8 + h];
    }
    msk[t] = (tok[base + t] == 0) ? 1.f : 0.f;
    __syncthreads();

    float q[8];
#pragma unroll
    for (int d = 0; d < 8; d++) q[d] = Q[(size_t)(base + t) * HDIM + d*8 + h];

    const float scale = 0.05773502691896258f;  // 1/sqrt(300)
    float m = -1e30f, ssum = 0.f, o[8];
#pragma unroll
    for (int d = 0; d < 8; d++) o[d] = 0.f;

    for (int k = 0; k < SEQ; k++) {
        float s = 0.f;
#pragma unroll
        for (int d = 0; d < 8; d++) s += q[d] * Ks[k][d];
        s *= scale;
        if (msk[k] != 0.f) s = -1e9f;
        if (s <= m) {
            float p = __expf(s - m);
            ssum += p;
#pragma unroll
            for (int d = 0; d < 8; d++) o[d] += p * Vs[k][d];
        } else {
            float corr = __expf(m - s);
            ssum = ssum * corr + 1.f;
#pragma unroll
            for (int d = 0; d < 8; d++) o[d] = o[d] * corr + Vs[k][d];
            m = s;
        }
    }
    float inv = 1.f / ssum;
#pragma unroll
    for (int d = 0; d < 8; d++)
        O[(size_t)(base + t) * HDIM + h*8 + d] = o[d] * inv;   // head-major concat
}

// ---------------- row LayerNorm over HID, ddof=1, eps 1e-8; optionally acc += y ----------------
template<bool ACC>
__global__ void ln_kernel(const float* __restrict__ in, float* __restrict__ outp,
                          const float* __restrict__ g, const float* __restrict__ bt,
                          float* __restrict__ accb) {
    const int row = blockIdx.x;
    const int t = threadIdx.x;       // 128
    __shared__ float red[128];
    const float* x = in + (size_t)row * HID;

    float v[3]; int c[3];
    float s = 0.f;
#pragma unroll
    for (int i = 0; i < 3; i++) {
        c[i] = t + i * 128;
        v[i] = (c[i] < HID) ? x[c[i]] : 0.f;
        s += v[i];
    }
    red[t] = s; __syncthreads();
    for (int st = 64; st > 0; st >>= 1) { if (t < st) red[t] += red[t + st]; __syncthreads(); }
    float mu = red[0] / HID;
    __syncthreads();
    float sq = 0.f;
#pragma unroll
    for (int i = 0; i < 3; i++) {
        if (c[i] < HID) { float d = v[i] - mu; sq += d * d; }
    }
    red[t] = sq; __syncthreads();
    for (int st = 64; st > 0; st >>= 1) { if (t < st) red[t] += red[t + st]; __syncthreads(); }
    float var = red[0] / (HID - 1);
    float inv = rsqrtf(var + 1e-8f);
    float gg = g[0], bb = bt[0];
#pragma unroll
    for (int i = 0; i < 3; i++) {
        if (c[i] < HID) {
            float y = gg * (v[i] - mu) * inv + bb;
            outp[(size_t)row * HID + c[i]] = y;
            if (ACC) accb[(size_t)row * HID + c[i]] += y;
        }
    }
}

// ---------------- sum over sequence: (B,S,HID) -> (B,HID) ----------------
__global__ void seqsum_kernel(const float* __restrict__ in, float* __restrict__ sums) {
    int b = blockIdx.x;
    int c = threadIdx.x;
    if (c < HID) {
        float a = 0.f;
        const float* p = in + (size_t)b * SEQ * HID + c;
        for (int s = 0; s < SEQ; s++) a += p[(size_t)s * HID];
        sums[b * HID + c] = a;
    }
}

// ---------------- classifier: (B,HID) @ (HID,NC) ----------------
__global__ void classify_kernel(const float* __restrict__ sums, const float* __restrict__ Vd,
                                float* __restrict__ logits) {
    int b = blockIdx.y;
    int c = blockIdx.x * 256 + threadIdx.x;
    __shared__ float srow[HID];
    for (int i = threadIdx.x; i < HID; i += 256) srow[i] = sums[b * HID + i];
    __syncthreads();
    if (c < NC) {
        float a = 0.f;
        for (int k = 0; k < HID; k++) a += srow[k] * Vd[(size_t)k * NC + c];
        logits[b * NC + c] = a;
    }
}

// ---------------- final LN (ddof=1) + softmax over NC ----------------
__global__ void final_kernel(const float* __restrict__ logits,
                             const float* __restrict__ gf, const float* __restrict__ bf,
                             float* __restrict__ outp) {
    const int b = blockIdx.x;
    const int t = threadIdx.x;   // 256
    __shared__ float buf[NC];
    __shared__ float red[256];
    const float* x = logits + (size_t)b * NC;

    float s = 0.f;
    for (int c = t; c < NC; c += 256) { float v = x[c]; buf[c] = v; s += v; }
    red[t] = s; __syncthreads();
    for (int st = 128; st > 0; st >>= 1) { if (t < st) red[t] += red[t + st]; __syncthreads(); }
    float mu = red[0] / NC;
    __syncthreads();

    float sq = 0.f;
    for (int c = t; c < NC; c += 256) { float d = buf[c] - mu; sq += d * d; }
    red[t] = sq; __syncthreads();
    for (int st = 128; st > 0; st >>= 1) { if (t < st) red[t] += red[t + st]; __syncthreads(); }
    float inv = rsqrtf(red[0] / (NC - 1) + 1e-8f);
    float gg = gf[0], bb = bf[0];
    __syncthreads();

    for (int c = t; c < NC; c += 256) buf[c] = gg * (buf[c] - mu) * inv + bb;
    __syncthreads();

    float mx = -1e30f;
    for (int c = t; c < NC; c += 256) mx = fmaxf(mx, buf[c]);
    red[t] = mx; __syncthreads();
    for (int st = 128; st > 0; st >>= 1) { if (t < st) red[t] = fmaxf(red[t], red[t + st]); __syncthreads(); }
    float rmax = red[0];
    __syncthreads();

    float es = 0.f;
    for (int c = t; c < NC; c += 256) es += __expf(buf[c] - rmax);
    red[t] = es; __syncthreads();
    for (int st = 128; st > 0; st >>= 1) { if (t < st) red[t] += red[t + st]; __syncthreads(); }
    float invs = 1.f / red[0];
    __syncthreads();

    for (int c = t; c < NC; c += 256) outp[(size_t)b * NC + c] = __expf(buf[c] - rmax) * invs;
}

// ---------------- launch ----------------
extern "C" void kernel_launch(void* const* d_in, const int* in_sizes, int n_in,
                              void* d_out, int out_size) {
    const int*   xk  = (const int*)  d_in[0];
    const float* emb = (const float*)d_in[1];
    const float* WQ  = (const float*)d_in[2];
    const float* WK  = (const float*)d_in[3];
    const float* WV  = (const float*)d_in[4];
    const float* WO  = (const float*)d_in[5];
    const float* W1  = (const float*)d_in[6];
    const float* b1  = (const float*)d_in[7];
    const float* W2  = (const float*)d_in[8];
    const float* b2  = (const float*)d_in[9];
    const float* g1  = (const float*)d_in[10];
    const float* be1 = (const float*)d_in[11];
    const float* g2  = (const float*)d_in[12];
    const float* be2 = (const float*)d_in[13];
    const float* Vd  = (const float*)d_in[14];
    const float* gf  = (const float*)d_in[15];
    const float* bf  = (const float*)d_in[16];
    float* outp = (float*)d_out;

    float *acc, *outb, *xa, *tmp, *q, *k, *v, *attn, *ffh, *pe, *sums, *logits;
    cudaGetSymbolAddress((void**)&acc,   g_acc);
    cudaGetSymbolAddress((void**)&outb,  g_out);
    cudaGetSymbolAddress((void**)&xa,    g_xa);
    cudaGetSymbolAddress((void**)&tmp,   g_tmp);
    cudaGetSymbolAddress((void**)&q,     g_q);
    cudaGetSymbolAddress((void**)&k,     g_k);
    cudaGetSymbolAddress((void**)&v,     g_v);
    cudaGetSymbolAddress((void**)&attn,  g_attn);
    cudaGetSymbolAddress((void**)&ffh,   g_ffh);
    cudaGetSymbolAddress((void**)&pe,    g_pe);
    cudaGetSymbolAddress((void**)&sums,  g_sums);
    cudaGetSymbolAddress((void**)&logits,g_logits);

    pe_kernel<<<SEQ, 128>>>(pe);
    embed_kernel<<<ROWS, 128>>>(xk, emb, pe, acc);

    const int MB = ROWS / 128;   // 128 m-blocks

    for (int l = 0; l < NL; l++) {
        const float* wq = WQ + (size_t)l * HID * HDIM;
        const float* wk = WK + (size_t)l * HID * HDIM;
        const float* wv = WV + (size_t)l * HID * HDIM;
        const float* wo = WO + (size_t)l * HDIM * HID;
        const float* w1 = W1 + (size_t)l * HID * FF;
        const float* w2 = W2 + (size_t)l * FF * HID;
        const float* bb1 = b1 + (size_t)l * FF;
        const float* bb2 = b2 + (size_t)l * HID;

        qkv_tc<<<dim3(1, MB, 3), 256>>>(acc, wq, wk, wv, q, k, v);

        attn_kernel<<<dim3(NH, BATCH), SEQ>>>(q, k, v, xk, attn);

        dim3 go((HID + 63) / 64, MB);
        gemm_tc<false,false,true><<<go, 256>>>(attn, wo, nullptr, acc, tmp, HID, HDIM);
        ln_kernel<false><<<ROWS, 128>>>(tmp, xa, g1 + l, be1 + l, nullptr);

        dim3 gf1((FF + 63) / 64, MB);
        gemm_tc<true,true,false><<<gf1, 256>>>(xa, w1, bb1, nullptr, ffh, FF, HID);
        gemm_tc<false,true,true><<<go, 256>>>(ffh, w2, bb2, xa, tmp, HID, FF);
        ln_kernel<true><<<ROWS, 128>>>(tmp, outb, g2 + l, be2 + l, acc);
    }

    seqsum_kernel<<<BATCH, 320>>>(outb, sums);
    classify_kernel<<<dim3((NC + 255) / 256, BATCH), 256>>>(sums, Vd, logits);
    final_kernel<<<BATCH, 256>>>(logits, gf, bf, outp);
}

// round 5
// speedup vs baseline: 2.9329x; 1.2862x over previous
#include <cuda_runtime.h>
#include <math.h>

#define SEQ   512
#define BATCH 32
#define ROWS  16384        // BATCH*SEQ
#define HID   300
#define HDIM  64
#define NH    8
#define DH    8
#define NL    6
#define FF    1200
#define NC    1000

// ---------------- scratch (static device globals; no allocation) ----------------
__device__ float g_acc [ROWS*HID];
__device__ float g_out [ROWS*HID];
__device__ float g_xa  [ROWS*HID];
__device__ float g_tmp [ROWS*HID];
__device__ float g_q   [ROWS*HDIM];
__device__ float g_k   [ROWS*HDIM];
__device__ float g_v   [ROWS*HDIM];
__device__ float g_attn[ROWS*HDIM];
__device__ float g_ffh [ROWS*FF];
__device__ float g_pe  [SEQ*HID];
__device__ float g_part[8*BATCH*HID];
__device__ float g_sums[BATCH*HID];
__device__ float g_logits[BATCH*NC];

// ---------------- positional encoding table ----------------
__global__ void pe_kernel(float* __restrict__ pe) {
    int s = blockIdx.x;
    for (int c = threadIdx.x; c < HID; c += blockDim.x) {
        double expo = (double)(c & ~1) / (double)HID;
        double ang  = (double)s * exp(-expo * 9.210340371976182736); // ln(10000)
        pe[s*HID + c] = (c & 1) ? (float)cos(ang) : (float)sin(ang);
    }
}

// acc = 2*emb[token] + PE   (x2 = emb+PE; acc = x2 + x1)
__global__ void embed_kernel(const int* __restrict__ tok,
                             const float* __restrict__ emb,
                             const float* __restrict__ pe,
                             float* __restrict__ accb) {
    int row = blockIdx.x;
    int s   = row & (SEQ - 1);
    long long t = tok[row];
    const float* er = emb + t * HID;
    const float* pr = pe + s * HID;
    for (int c = threadIdx.x; c < HID; c += blockDim.x) {
        accb[row*HID + c] = 2.f * er[c] + pr[c];
    }
}

// ================= tf32 tensor-core GEMM, cp.async double-buffered =================
// C(MxN) = A(MxK, row-major) @ B(KxN, row-major) [+bias][+res][relu]
// Block tile 128 x BN, BK=16, 256 threads = 8 warps (4x2), warp tile 32 x BN/2.

__device__ __forceinline__ void mma_tf32(float d[4], const unsigned a[4],
                                         const unsigned b[2], const float c[4]) {
    asm volatile(
        "mma.sync.aligned.m16n8k8.row.col.f32.tf32.tf32.f32 "
        "{%0,%1,%2,%3}, {%4,%5,%6,%7}, {%8,%9}, {%10,%11,%12,%13};\n"
        : "=f"(d[0]), "=f"(d[1]), "=f"(d[2]), "=f"(d[3])
        : "r"(a[0]), "r"(a[1]), "r"(a[2]), "r"(a[3]),
          "r"(b[0]), "r"(b[1]),
          "f"(c[0]), "f"(c[1]), "f"(c[2]), "f"(c[3]));
}

__device__ __forceinline__ void cp16(void* smem, const void* gmem) {
    unsigned saddr = (unsigned)__cvta_generic_to_shared(smem);
    asm volatile("cp.async.cg.shared.global [%0], [%1], 16;" :: "r"(saddr), "l"(gmem));
}

#define AS_LD 20    // 128x16 A tile, m-major rows padded to 20 floats (conflict-free frag loads)

template<int BN, bool RELU, bool BIAS, bool RES>
__device__ __forceinline__ void gemm_body(const float* __restrict__ A,
                                          const float* __restrict__ B,
                                          const float* __restrict__ bias,
                                          const float* __restrict__ res,
                                          float* __restrict__ C,
                                          int N, int K, int bm, int bn) {
    constexpr int BS_LD = BN + 8;     // %32 == 8 -> conflict-free
    constexpr int NT = BN / 16;       // n-tiles of 8 per warp
    __shared__ float As[2][128][AS_LD];
    __shared__ float Bs[2][16][BS_LD];

    const int tid  = threadIdx.x;
    const int lane = tid & 31, warp = tid >> 5;
    const int gid  = lane >> 2, tig = lane & 3;
    const int rowb = (warp & 3) * 32;          // 4 warps over M
    const int nb   = (warp >> 2) * (BN / 2);   // 2 warps over N

    float acc[2][NT][4];
#pragma unroll
    for (int mt = 0; mt < 2; mt++)
#pragma unroll
        for (int nt = 0; nt < NT; nt++)
#pragma unroll
            for (int i = 0; i < 4; i++) acc[mt][nt][i] = 0.f;

    const int S = (K + 15) / 16;

    // stage loader: issues one cp.async group (A 128x16, B 16xBN) for stage s -> buf
    auto issue = [&](int s, int buf) {
        int k0 = s * 16;
        // A tile: 512 float4 chunks, 2 per thread  (K % 4 == 0 -> chunk fully in or out)
#pragma unroll
        for (int j = 0; j < 2; j++) {
            int idx = tid + j * 256;
            int r = idx >> 2, c4 = (idx & 3) * 4;
            float* dst = &As[buf][r][c4];
            if (k0 + c4 < K) cp16(dst, A + (size_t)(bm + r) * K + k0 + c4);
            else *(float4*)dst = make_float4(0.f, 0.f, 0.f, 0.f);
        }
        // B tile: 4*BN chunks, BN/64 per thread  (N % 4 == 0)
#pragma unroll
        for (int j = 0; j < BN / 64; j++) {
            int idx = tid + j * 256;
            int r = idx / (BN / 4);
            int c4 = (idx % (BN / 4)) * 4;
            float* dst = &Bs[buf][r][c4];
            int gr = k0 + r, gc = bn + c4;
            if (gr < K && gc < N) cp16(dst, B + (size_t)gr * N + gc);
            else *(float4*)dst = make_float4(0.f, 0.f, 0.f, 0.f);
        }
        asm volatile("cp.async.commit_group;");
    };

    issue(0, 0);

    for (int s = 0; s < S; s++) {
        asm volatile("cp.async.wait_group 0;");
        __syncthreads();
        if (s + 1 < S) issue(s + 1, (s + 1) & 1);

        const float (*as)[AS_LD] = As[s & 1];
        const float (*bs)[BS_LD] = Bs[s & 1];
#pragma unroll
        for (int ks = 0; ks < 2; ks++) {
            const int kk = ks * 8;
            unsigned af[2][4], bf[NT][2];
#pragma unroll
            for (int mt = 0; mt < 2; mt++) {
                int r0 = rowb + mt * 16 + gid;
                af[mt][0] = __float_as_uint(as[r0    ][kk + tig    ]);
                af[mt][1] = __float_as_uint(as[r0 + 8][kk + tig    ]);
                af[mt][2] = __float_as_uint(as[r0    ][kk + tig + 4]);
                af[mt][3] = __float_as_uint(as[r0 + 8][kk + tig + 4]);
            }
#pragma unroll
            for (int nt = 0; nt < NT; nt++) {
                int c0 = nb + nt * 8 + gid;
                bf[nt][0] = __float_as_uint(bs[kk + tig    ][c0]);
                bf[nt][1] = __float_as_uint(bs[kk + tig + 4][c0]);
            }
#pragma unroll
            for (int mt = 0; mt < 2; mt++)
#pragma unroll
                for (int nt = 0; nt < NT; nt++)
                    mma_tf32(acc[mt][nt], af[mt], bf[nt], acc[mt][nt]);
        }
    }

    // epilogue
#pragma unroll
    for (int mt = 0; mt < 2; mt++) {
        int row0 = bm + rowb + mt * 16 + gid;
#pragma unroll
        for (int nt = 0; nt < NT; nt++) {
            int col = bn + nb + nt * 8 + 2 * tig;
#pragma unroll
            for (int half = 0; half < 2; half++) {
                int row = row0 + half * 8;
                float v0 = acc[mt][nt][half * 2 + 0];
                float v1 = acc[mt][nt][half * 2 + 1];
                if (col < N) {
                    if (BIAS) v0 += bias[col];
                    if (RES)  v0 += res[(size_t)row * N + col];
                    if (RELU) v0 = fmaxf(v0, 0.f);
                    C[(size_t)row * N + col] = v0;
                }
                if (col + 1 < N) {
                    if (BIAS) v1 += bias[col + 1];
                    if (RES)  v1 += res[(size_t)row * N + col + 1];
                    if (RELU) v1 = fmaxf(v1, 0.f);
                    C[(size_t)row * N + col + 1] = v1;
                }
            }
        }
    }
}

template<int BN, bool RELU, bool BIAS, bool RES>
__global__ void __launch_bounds__(256) gemm_tc(const float* __restrict__ A,
                                               const float* __restrict__ B,
                                               const float* __restrict__ bias,
                                               const float* __restrict__ res,
                                               float* __restrict__ C,
                                               int N, int K) {
    gemm_body<BN, RELU, BIAS, RES>(A, B, bias, res, C, N, K,
                                   blockIdx.y * 128, blockIdx.x * BN);
}

// fused QKV: grid (1, M/128, 3)
__global__ void __launch_bounds__(256) qkv_tc(const float* __restrict__ A,
                                              const float* __restrict__ WQa,
                                              const float* __restrict__ WKa,
                                              const float* __restrict__ WVa,
                                              float* __restrict__ Q,
                                              float* __restrict__ Kk,
                                              float* __restrict__ V) {
    const float* B = (blockIdx.z == 0) ? WQa : (blockIdx.z == 1) ? WKa : WVa;
    float* C = (blockIdx.z == 0) ? Q : (blockIdx.z == 1) ? Kk : V;
    gemm_body<64, false, false, false>(A, B, nullptr, nullptr, C, HDIM, HID,
                                       blockIdx.y * 128, 0);
}

// ---------------- attention: block = (head, batch, q-half), branch-free softmax ----------------
__global__ void __launch_bounds__(256) attn_kernel(const float* __restrict__ Q,
                                                   const float* __restrict__ Kb,
                                                   const float* __restrict__ Vb,
                                                   const int* __restrict__ tok,
                                                   float* __restrict__ O) {
    const int h = blockIdx.x;
    const int b = blockIdx.y;
    const int base = b * SEQ;
    __shared__ float Ks[SEQ][8];
    __shared__ float Vs[SEQ][8];
    __shared__ float addm[SEQ];
    const int t = threadIdx.x;       // 256

    for (int kk = t; kk < SEQ; kk += 256) {
        const float* kp = Kb + (size_t)(base + kk) * HDIM + h;
        const float* vp = Vb + (size_t)(base + kk) * HDIM + h;
#pragma unroll
        for (int d = 0; d < 8; d++) {
            Ks[kk][d] = kp[d * 8];
            Vs[kk][d] = vp[d * 8];
        }
        addm[kk] = (tok[base + kk] == 0) ? -1e9f : 0.f;
    }
    __syncthreads();

    const int qi = blockIdx.z * 256 + t;
    const float scale = 0.05773502691896258f;  // 1/sqrt(300)
    float q[8];
    const float* qp = Q + (size_t)(base + qi) * HDIM + h;
#pragma unroll
    for (int d = 0; d < 8; d++) q[d] = qp[d * 8] * scale;

    float ssum = 0.f, o[8];
#pragma unroll
    for (int d = 0; d < 8; d++) o[d] = 0.f;

    for (int k = 0; k < SEQ; k++) {
        float4 k0 = *(const float4*)&Ks[k][0];
        float4 k1 = *(const float4*)&Ks[k][4];
        float s = addm[k];
        s += q[0]*k0.x + q[1]*k0.y + q[2]*k0.z + q[3]*k0.w
           + q[4]*k1.x + q[5]*k1.y + q[6]*k1.z + q[7]*k1.w;
        float p = __expf(s);                     // masked -> exp(-1e9) == 0
        ssum += p;
        float4 v0 = *(const float4*)&Vs[k][0];
        float4 v1 = *(const float4*)&Vs[k][4];
        o[0] += p * v0.x; o[1] += p * v0.y; o[2] += p * v0.z; o[3] += p * v0.w;
        o[4] += p * v1.x; o[5] += p * v1.y; o[6] += p * v1.z; o[7] += p * v1.w;
    }
    float inv = 1.f / ssum;
    float* op = O + (size_t)(base + qi) * HDIM + h * 8;   // head-major concat
#pragma unroll
    for (int d = 0; d < 8; d++) op[d] = o[d] * inv;
}

// ---------------- LayerNorm: warp per row, shuffle reductions ----------------
template<bool ACC>
__global__ void __launch_bounds__(256) ln_kernel(const float* __restrict__ in,
                                                 float* __restrict__ outp,
                                                 const float* __restrict__ g,
                                                 const float* __restrict__ bt,
                                                 float* __restrict__ accb) {
    const int warp = threadIdx.x >> 5, lane = threadIdx.x & 31;
    const int row = blockIdx.x * 8 + warp;
    const float* x = in + (size_t)row * HID;

    float v[10];
    float s = 0.f;
#pragma unroll
    for (int i = 0; i < 10; i++) {
        int c = lane + i * 32;
        v[i] = (c < HID) ? x[c] : 0.f;
        s += v[i];
    }
#pragma unroll
    for (int o = 16; o; o >>= 1) s += __shfl_xor_sync(0xffffffffu, s, o);
    float mu = s / HID;

    float sq = 0.f;
#pragma unroll
    for (int i = 0; i < 10; i++) {
        int c = lane + i * 32;
        if (c < HID) { float d = v[i] - mu; sq += d * d; }
    }
#pragma unroll
    for (int o = 16; o; o >>= 1) sq += __shfl_xor_sync(0xffffffffu, sq, o);
    float inv = rsqrtf(sq / (HID - 1) + 1e-8f);

    float gg = g[0], bb = bt[0];
#pragma unroll
    for (int i = 0; i < 10; i++) {
        int c = lane + i * 32;
        if (c < HID) {
            float y = gg * (v[i] - mu) * inv + bb;
            outp[(size_t)row * HID + c] = y;
            if (ACC) accb[(size_t)row * HID + c] += y;
        }
    }
}

// ---------------- sum over sequence, two-stage (deterministic) ----------------
__global__ void seqsum1(const float* __restrict__ in, float* __restrict__ part) {
    int b = blockIdx.x, ch = blockIdx.y, c = threadIdx.x;
    if (c < HID) {
        float a = 0.f;
        const float* p = in + ((size_t)b * SEQ + ch * 64) * HID + c;
        for (int s = 0; s < 64; s++) a += p[(size_t)s * HID];
        part[((size_t)ch * BATCH + b) * HID + c] = a;
    }
}
__global__ void seqsum2(const float* __restrict__ part, float* __restrict__ sums) {
    int b = blockIdx.x, c = threadIdx.x;
    if (c < HID) {
        float a = 0.f;
#pragma unroll
        for (int ch = 0; ch < 8; ch++) a += part[((size_t)ch * BATCH + b) * HID + c];
        sums[b * HID + c] = a;
    }
}

// ---------------- classifier: (B,HID) @ (HID,NC) ----------------
__global__ void classify_kernel(const float* __restrict__ sums, const float* __restrict__ Vd,
                                float* __restrict__ logits) {
    int b = blockIdx.y;
    int c = blockIdx.x * 256 + threadIdx.x;
    __shared__ float srow[HID];
    for (int i = threadIdx.x; i < HID; i += 256) srow[i] = sums[b * HID + i];
    __syncthreads();
    if (c < NC) {
        float a = 0.f;
        for (int k = 0; k < HID; k++) a += srow[k] * Vd[(size_t)k * NC + c];
        logits[b * NC + c] = a;
    }
}

// ---------------- final LN (ddof=1) + softmax over NC ----------------
__global__ void final_kernel(const float* __restrict__ logits,
                             const float* __restrict__ gf, const float* __restrict__ bf,
                             float* __restrict__ outp) {
    const int b = blockIdx.x;
    const int t = threadIdx.x;   // 256
    __shared__ float buf[NC];
    __shared__ float red[256];
    const float* x = logits + (size_t)b * NC;

    float s = 0.f;
    for (int c = t; c < NC; c += 256) { float v = x[c]; buf[c] = v; s += v; }
    red[t] = s; __syncthreads();
    for (int st = 128; st > 0; st >>= 1) { if (t < st) red[t] += red[t + st]; __syncthreads(); }
    float mu = red[0] / NC;
    __syncthreads();

    float sq = 0.f;
    for (int c = t; c < NC; c += 256) { float d = buf[c] - mu; sq += d * d; }
    red[t] = sq; __syncthreads();
    for (int st = 128; st > 0; st >>= 1) { if (t < st) red[t] += red[t + st]; __syncthreads(); }
    float inv = rsqrtf(red[0] / (NC - 1) + 1e-8f);
    float gg = gf[0], bb = bf[0];
    __syncthreads();

    for (int c = t; c < NC; c += 256) buf[c] = gg * (buf[c] - mu) * inv + bb;
    __syncthreads();

    float mx = -1e30f;
    for (int c = t; c < NC; c += 256) mx = fmaxf(mx, buf[c]);
    red[t] = mx; __syncthreads();
    for (int st = 128; st > 0; st >>= 1) { if (t < st) red[t] = fmaxf(red[t], red[t + st]); __syncthreads(); }
    float rmax = red[0];
    __syncthreads();

    float es = 0.f;
    for (int c = t; c < NC; c += 256) es += __expf(buf[c] - rmax);
    red[t] = es; __syncthreads();
    for (int st = 128; st > 0; st >>= 1) { if (t < st) red[t] += red[t + st]; __syncthreads(); }
    float invs = 1.f / red[0];
    __syncthreads();

    for (int c = t; c < NC; c += 256) outp[(size_t)b * NC + c] = __expf(buf[c] - rmax) * invs;
}

// ---------------- launch ----------------
extern "C" void kernel_launch(void* const* d_in, const int* in_sizes, int n_in,
                              void* d_out, int out_size) {
    const int*   xk  = (const int*)  d_in[0];
    const float* emb = (const float*)d_in[1];
    const float* WQ  = (const float*)d_in[2];
    const float* WK  = (const float*)d_in[3];
    const float* WV  = (const float*)d_in[4];
    const float* WO  = (const float*)d_in[5];
    const float* W1  = (const float*)d_in[6];
    const float* b1  = (const float*)d_in[7];
    const float* W2  = (const float*)d_in[8];
    const float* b2  = (const float*)d_in[9];
    const float* g1  = (const float*)d_in[10];
    const float* be1 = (const float*)d_in[11];
    const float* g2  = (const float*)d_in[12];
    const float* be2 = (const float*)d_in[13];
    const float* Vd  = (const float*)d_in[14];
    const float* gf  = (const float*)d_in[15];
    const float* bf  = (const float*)d_in[16];
    float* outp = (float*)d_out;

    float *acc, *outb, *xa, *tmp, *q, *k, *v, *attn, *ffh, *pe, *part, *sums, *logits;
    cudaGetSymbolAddress((void**)&acc,   g_acc);
    cudaGetSymbolAddress((void**)&outb,  g_out);
    cudaGetSymbolAddress((void**)&xa,    g_xa);
    cudaGetSymbolAddress((void**)&tmp,   g_tmp);
    cudaGetSymbolAddress((void**)&q,     g_q);
    cudaGetSymbolAddress((void**)&k,     g_k);
    cudaGetSymbolAddress((void**)&v,     g_v);
    cudaGetSymbolAddress((void**)&attn,  g_attn);
    cudaGetSymbolAddress((void**)&ffh,   g_ffh);
    cudaGetSymbolAddress((void**)&pe,    g_pe);
    cudaGetSymbolAddress((void**)&part,  g_part);
    cudaGetSymbolAddress((void**)&sums,  g_sums);
    cudaGetSymbolAddress((void**)&logits,g_logits);

    pe_kernel<<<SEQ, 128>>>(pe);
    embed_kernel<<<ROWS, 128>>>(xk, emb, pe, acc);

    const int MB = ROWS / 128;   // 128 m-blocks

    for (int l = 0; l < NL; l++) {
        const float* wq = WQ + (size_t)l * HID * HDIM;
        const float* wk = WK + (size_t)l * HID * HDIM;
        const float* wv = WV + (size_t)l * HID * HDIM;
        const float* wo = WO + (size_t)l * HDIM * HID;
        const float* w1 = W1 + (size_t)l * HID * FF;
        const float* w2 = W2 + (size_t)l * FF * HID;
        const float* bb1 = b1 + (size_t)l * FF;
        const float* bb2 = b2 + (size_t)l * HID;

        qkv_tc<<<dim3(1, MB, 3), 256>>>(acc, wq, wk, wv, q, k, v);

        attn_kernel<<<dim3(NH, BATCH, 2), 256>>>(q, k, v, xk, attn);

        dim3 go((HID + 63) / 64, MB);
        gemm_tc<64, false,false,true><<<go, 256>>>(attn, wo, nullptr, acc, tmp, HID, HDIM);
        ln_kernel<false><<<ROWS/8, 256>>>(tmp, xa, g1 + l, be1 + l, nullptr);

        dim3 gf1((FF + 127) / 128, MB);
        gemm_tc<128, true,true,false><<<gf1, 256>>>(xa, w1, bb1, nullptr, ffh, FF, HID);
        gemm_tc<64, false,true,true><<<go, 256>>>(ffh, w2, bb2, xa, tmp, HID, FF);
        ln_kernel<true><<<ROWS/8, 256>>>(tmp, outb, g2 + l, be2 + l, acc);
    }

    seqsum1<<<dim3(BATCH, 8), 320>>>(outb, part);
    seqsum2<<<BATCH, 320>>>(part, sums);
    classify_kernel<<<dim3((NC + 255) / 256, BATCH), 256>>>(sums, Vd, logits);
    final_kernel<<<BATCH, 256>>>(logits, gf, bf, outp);
}